// round 1
// baseline (speedup 1.0000x reference)
#include <cuda_runtime.h>
#include <math.h>

#define NH   256     // B*H = 8*32 heads
#define SLEN 4096
#define DIM  128
#define RSEL 16
#define KSEL 256

// ---- device scratch (no allocations allowed) ----
__device__ float g_qmask[NH * DIM];   // Q with non-top-r dims zeroed
__device__ float g_rscale[NH];        // 1/scale
__device__ float g_vmean[NH * DIM];   // un-normalized V column sums
__device__ float g_scores[NH * SLEN]; // QK_hat / scale

__device__ __forceinline__ unsigned fkey(float f) {
    unsigned u = __float_as_uint(f);
    return (u & 0x80000000u) ? ~u : (u | 0x80000000u);  // order-preserving float->uint
}

// ============================================================
// K1: per head — top-16 |Q| dims, scale, masked Q; zero vmean
// grid NH, block 128
// ============================================================
__global__ void prep_kernel(const float* __restrict__ Q) {
    int h = blockIdx.x, t = threadIdx.x;
    __shared__ float aq[DIM];
    __shared__ float rv[DIM];
    __shared__ int   ri[DIM];
    __shared__ unsigned char sel[DIM];
    __shared__ float s_sumall, s_sumtop;

    float q = Q[h * DIM + t];
    float a = fabsf(q);
    aq[t] = a; sel[t] = 0;
    g_vmean[h * DIM + t] = 0.f;   // zero before vmean_kernel atomics (stream-ordered)
    rv[t] = a;
    __syncthreads();
    for (int s = 64; s > 0; s >>= 1) { if (t < s) rv[t] += rv[t + s]; __syncthreads(); }
    if (t == 0) s_sumall = rv[0];
    __syncthreads();

    float sumtop = 0.f;
    for (int it = 0; it < RSEL; it++) {
        rv[t] = aq[t]; ri[t] = t;
        __syncthreads();
        for (int s = 64; s > 0; s >>= 1) {
            if (t < s) {
                float v2 = rv[t + s]; int i2 = ri[t + s];
                if (v2 > rv[t] || (v2 == rv[t] && i2 < ri[t])) { rv[t] = v2; ri[t] = i2; }
            }
            __syncthreads();
        }
        if (t == 0) { sel[ri[0]] = 1; sumtop += rv[0]; aq[ri[0]] = -1.f; }
        __syncthreads();
    }
    if (t == 0) s_sumtop = sumtop;
    __syncthreads();

    g_qmask[h * DIM + t] = sel[t] ? q : 0.f;
    if (t == 0) g_rscale[h] = rsqrtf((float)DIM * s_sumtop / s_sumall);
}

// ============================================================
// K2: V mean partial sums (balanced). grid NH*8, block 256
// ============================================================
__global__ __launch_bounds__(256) void vmean_kernel(const float* __restrict__ Vg) {
    int bid = blockIdx.x; int h = bid >> 3; int chunk = bid & 7;
    int t = threadIdx.x; int g = t >> 5; int lane = t & 31;
    const float4* Vr = (const float4*)(Vg + (size_t)h * SLEN * DIM);
    float4 acc = make_float4(0.f, 0.f, 0.f, 0.f);
    int base = chunk * 512;
#pragma unroll 4
    for (int r = g; r < 512; r += 8) {
        float4 v = Vr[(size_t)(base + r) * 32 + lane];
        acc.x += v.x; acc.y += v.y; acc.z += v.z; acc.w += v.w;
    }
    __shared__ float4 buf[8][32];
    buf[g][lane] = acc;
    __syncthreads();
    if (t < 32) {
        float4 s = buf[0][t];
#pragma unroll
        for (int i = 1; i < 8; i++) {
            float4 v = buf[i][t];
            s.x += v.x; s.y += v.y; s.z += v.z; s.w += v.w;
        }
        float* dst = g_vmean + h * DIM + t * 4;
        atomicAdd(dst + 0, s.x); atomicAdd(dst + 1, s.y);
        atomicAdd(dst + 2, s.z); atomicAdd(dst + 3, s.w);
    }
}

// ============================================================
// K3: scores[s] = dot(qmask, K[s]) * (1/scale). Dense coalesced
// read of all of K. grid NH*4, block 512 (16 warps).
// ============================================================
__global__ __launch_bounds__(512) void score_kernel(const float* __restrict__ Kg) {
    int bid = blockIdx.x; int h = bid >> 2; int chunk = bid & 3;
    int t = threadIdx.x; int w = t >> 5; int lane = t & 31;
    __shared__ float4 qs4[32];
    __shared__ float s_rs;
    if (t < 32) qs4[t] = ((const float4*)(g_qmask + h * DIM))[t];
    if (t == 0) s_rs = g_rscale[h];
    __syncthreads();
    float4 qv = qs4[lane];
    float rs = s_rs;
    const float4* Kr = (const float4*)(Kg + (size_t)h * SLEN * DIM);
    float* outp = g_scores + h * SLEN + chunk * 1024;
    int base = chunk * 1024;

    for (int it = 0; it < 64; it += 4) {   // warp w owns rows w+16*m; 4 rows per iter for MLP
        int r0 = w + 16 * it;
        float4 k0 = Kr[(size_t)(base + r0     ) * 32 + lane];
        float4 k1 = Kr[(size_t)(base + r0 + 16) * 32 + lane];
        float4 k2 = Kr[(size_t)(base + r0 + 32) * 32 + lane];
        float4 k3 = Kr[(size_t)(base + r0 + 48) * 32 + lane];
        float d0 = qv.x * k0.x + qv.y * k0.y + qv.z * k0.z + qv.w * k0.w;
        float d1 = qv.x * k1.x + qv.y * k1.y + qv.z * k1.z + qv.w * k1.w;
        float d2 = qv.x * k2.x + qv.y * k2.y + qv.z * k2.z + qv.w * k2.w;
        float d3 = qv.x * k3.x + qv.y * k3.y + qv.z * k3.z + qv.w * k3.w;
#pragma unroll
        for (int off = 16; off; off >>= 1) {
            d0 += __shfl_xor_sync(0xffffffffu, d0, off);
            d1 += __shfl_xor_sync(0xffffffffu, d1, off);
            d2 += __shfl_xor_sync(0xffffffffu, d2, off);
            d3 += __shfl_xor_sync(0xffffffffu, d3, off);
        }
        if (lane == 0) {
            outp[r0] = d0 * rs; outp[r0 + 16] = d1 * rs;
            outp[r0 + 32] = d2 * rs; outp[r0 + 48] = d3 * rs;
        }
    }
}

// ============================================================
// K4: per head — softmax stats over 4096 scores, radix top-256,
// alpha, dense 256-row attention, combine with V_mean.
// grid NH, block 512
// ============================================================
__global__ __launch_bounds__(512) void final_kernel(
    const float* __restrict__ Q, const float* __restrict__ Kg,
    const float* __restrict__ Vg, float* __restrict__ out)
{
    __shared__ float sc[SLEN];      // 16KB
    __shared__ float red[512];
    __shared__ int   hist[256];
    __shared__ int   scn[256];
    __shared__ int   idxs[KSEL];
    __shared__ float wts[KSEL];
    __shared__ float qsh[DIM];
    __shared__ float4 ybuf[16][32]; // 8KB
    __shared__ unsigned s_prefix;
    __shared__ int s_need, s_cntA, s_cntB;
    __shared__ float s_mx, s_Z, s_alpha, s_m2, s_Z2;

    int h = blockIdx.x, t = threadIdx.x;
    for (int i = t; i < SLEN; i += 512) sc[i] = g_scores[h * SLEN + i];
    if (t < DIM) qsh[t] = Q[h * DIM + t];
    __syncthreads();

    // ---- max over 4096 ----
    float mx = -3.4e38f;
    for (int i = t; i < SLEN; i += 512) mx = fmaxf(mx, sc[i]);
    red[t] = mx; __syncthreads();
    for (int s = 256; s > 0; s >>= 1) { if (t < s) red[t] = fmaxf(red[t], red[t + s]); __syncthreads(); }
    if (t == 0) s_mx = red[0];
    __syncthreads();
    mx = s_mx;

    // ---- Z = sum exp ----
    float z = 0.f;
    for (int i = t; i < SLEN; i += 512) z += __expf(sc[i] - mx);
    __syncthreads();
    red[t] = z; __syncthreads();
    for (int s = 256; s > 0; s >>= 1) { if (t < s) red[t] += red[t + s]; __syncthreads(); }
    if (t == 0) s_Z = red[0];
    __syncthreads();

    // ---- exact radix top-KSEL threshold on fkey(score) ----
    unsigned prefix = 0; int need = KSEL;
    for (int pass = 0; pass < 4; pass++) {
        int shift = 24 - 8 * pass;
        if (t < 256) hist[t] = 0;
        __syncthreads();
        for (int i = t; i < SLEN; i += 512) {
            unsigned u = fkey(sc[i]);
            unsigned hb = (pass == 0) ? 0u : (u >> (shift + 8));
            unsigned pb = (pass == 0) ? 0u : (prefix >> (shift + 8));
            if (hb == pb) atomicAdd(&hist[(u >> shift) & 255], 1);
        }
        __syncthreads();
        if (t < 256) scn[t] = hist[t];
        __syncthreads();
        for (int off = 1; off < 256; off <<= 1) {     // inclusive suffix sum
            int v = 0;
            if (t < 256) v = scn[t] + ((t + off < 256) ? scn[t + off] : 0);
            __syncthreads();
            if (t < 256) scn[t] = v;
            __syncthreads();
        }
        if (t < 256) {
            int above = (t + 1 < 256) ? scn[t + 1] : 0;   // strictly higher buckets
            if (above < need && above + hist[t] >= need) {
                s_prefix = prefix | ((unsigned)t << shift);
                s_need = need - above;
            }
        }
        __syncthreads();
        prefix = s_prefix; need = s_need;
        __syncthreads();
    }
    unsigned T = prefix;

    // ---- compact indices: all > T, then fill with == T ----
    if (t == 0) s_cntA = 0;
    __syncthreads();
    for (int i = t; i < SLEN; i += 512)
        if (fkey(sc[i]) > T) { int p = atomicAdd(&s_cntA, 1); if (p < KSEL) idxs[p] = i; }
    __syncthreads();
    if (t == 0) s_cntB = s_cntA;
    __syncthreads();
    for (int i = t; i < SLEN; i += 512)
        if (fkey(sc[i]) == T) { int p = atomicAdd(&s_cntB, 1); if (p < KSEL) idxs[p] = i; }
    __syncthreads();

    // ---- alpha = sum of top-k softmax probs ----
    float an = (t < KSEL) ? __expf(sc[idxs[t]] - mx) : 0.f;
    red[t] = an; __syncthreads();
    for (int s = 256; s > 0; s >>= 1) { if (t < s) red[t] += red[t + s]; __syncthreads(); }
    if (t == 0) s_alpha = red[0] / s_Z;
    __syncthreads();

    // ---- full logits over selected 256 rows ----
    int w = t >> 5, lane = t & 31;
    float4 qv = ((float4*)qsh)[lane];
    const float4* Kr = (const float4*)(Kg + (size_t)h * SLEN * DIM);
#pragma unroll 4
    for (int it = 0; it < 16; it++) {
        int j = w * 16 + it;
        int row = idxs[j];
        float4 kv = Kr[(size_t)row * 32 + lane];
        float d = qv.x * kv.x + qv.y * kv.y + qv.z * kv.z + qv.w * kv.w;
#pragma unroll
        for (int off = 16; off; off >>= 1) d += __shfl_xor_sync(0xffffffffu, d, off);
        if (lane == 0) wts[j] = d * 0.08838834764831845f;  // 1/sqrt(128)
    }
    __syncthreads();

    // ---- softmax over 256 ----
    float l = (t < KSEL) ? wts[t] : -3.4e38f;
    red[t] = l; __syncthreads();
    for (int s = 256; s > 0; s >>= 1) { if (t < s) red[t] = fmaxf(red[t], red[t + s]); __syncthreads(); }
    if (t == 0) s_m2 = red[0];
    __syncthreads();
    float e = (t < KSEL) ? __expf(l - s_m2) : 0.f;
    red[t] = e; __syncthreads();
    for (int s = 256; s > 0; s >>= 1) { if (t < s) red[t] += red[t + s]; __syncthreads(); }
    if (t == 0) s_Z2 = red[0];
    __syncthreads();
    if (t < KSEL) wts[t] = e / s_Z2;
    __syncthreads();

    // ---- y = sum_j w_j V[idx_j] ----
    int quad = t & 31, grp = t >> 5;
    const float4* Vr = (const float4*)(Vg + (size_t)h * SLEN * DIM);
    float4 acc = make_float4(0.f, 0.f, 0.f, 0.f);
#pragma unroll 4
    for (int j = grp; j < KSEL; j += 16) {
        float wj = wts[j]; int row = idxs[j];
        float4 v = Vr[(size_t)row * 32 + quad];
        acc.x += wj * v.x; acc.y += wj * v.y; acc.z += wj * v.z; acc.w += wj * v.w;
    }
    ybuf[grp][quad] = acc;
    __syncthreads();
    if (t < 32) {
        float4 y = ybuf[0][t];
#pragma unroll
        for (int i = 1; i < 16; i++) {
            float4 v = ybuf[i][t];
            y.x += v.x; y.y += v.y; y.z += v.z; y.w += v.w;
        }
        float alpha = s_alpha;
        const float inv = 1.f / (float)SLEN;
        float4 vm;
        vm.x = g_vmean[h * DIM + t * 4 + 0] * inv;
        vm.y = g_vmean[h * DIM + t * 4 + 1] * inv;
        vm.z = g_vmean[h * DIM + t * 4 + 2] * inv;
        vm.w = g_vmean[h * DIM + t * 4 + 3] * inv;
        float4 o;
        o.x = vm.x + alpha * (y.x - vm.x);
        o.y = vm.y + alpha * (y.y - vm.y);
        o.z = vm.z + alpha * (y.z - vm.z);
        o.w = vm.w + alpha * (y.w - vm.w);
        ((float4*)out)[h * 32 + t] = o;
    }
}

extern "C" void kernel_launch(void* const* d_in, const int* in_sizes, int n_in,
                              void* d_out, int out_size) {
    const float* Q = (const float*)d_in[0];
    const float* K = (const float*)d_in[1];
    const float* V = (const float*)d_in[2];
    // d_in[3] = mask (all true for this problem), d_in[4]=r, d_in[5]=k (compile-time constants)
    float* out = (float*)d_out;

    prep_kernel<<<NH, DIM>>>(Q);              // also zeroes g_vmean (stream-ordered)
    vmean_kernel<<<NH * 8, 256>>>(V);
    score_kernel<<<NH * 4, 512>>>(K);
    final_kernel<<<NH, 512>>>(Q, K, V, out);
}